// round 3
// baseline (speedup 1.0000x reference)
#include <cuda_runtime.h>

#define BB 64
#define HH 256
#define WW 256
#define CC 3
#define KK 20
#define HWPIX (HH * WW)

// k_warp tiling: 16 rows x 64 cols per block, 4 col-groups x 16 row-groups
#define TR 16
#define TC 64
#define NBLK_PER_IMG 64          // 16 * 4
// staged input window (bounds from zoom<=1.15, |rot|<=0.05, |shy|<=0.2)
#define WR 26                    // rows  (need <= 24)
#define WC 84                    // cols  (need <= 81)
#define WROWF (WC * 3)           // floats per window row = 252

// Scratch (device globals: allowed, no allocation)
__device__ float g_partial[BB][NBLK_PER_IMG][3];
__device__ float g_mean[BB][3];
__device__ unsigned g_emask[BB][HH][8];   // per-row 256-bit erase mask
__device__ unsigned g_bmask[BB][HH][8];   // per-row 256-bit blot mask

// ---------------------------------------------------------------------------
// Kernel 1: smem-staged affine bilinear warp -> out, + per-block channel sums
// ---------------------------------------------------------------------------
__global__ __launch_bounds__(256) void k_warp(
    const float* __restrict__ img,
    const float* __restrict__ zoom, const float* __restrict__ rot,
    const float* __restrict__ shy,  const float* __restrict__ ty,
    const float* __restrict__ tx,
    float* __restrict__ out)
{
    const int b  = blockIdx.z;
    const int ry = blockIdx.y * TR;      // first output row of tile
    const int cx = blockIdx.x * TC;      // first output col of tile
    const int t  = threadIdx.x;          // 0..255

    const float z  = zoom[b];
    const float r  = rot[b];
    const float sh = shy[b];
    const float co = cosf(r), si = sinf(r);
    const float a0 = z * co;
    const float a1 = -z * (si + sh);
    const float b0 = z * si;
    const float b1 = z * co;
    const float ccx = (WW - 1) * 0.5f, ccy = (HH - 1) * 0.5f;
    const float a2 = -a0 * ccx - a1 * ccy + ccx + tx[b];
    const float b2 = -b0 * ccx - b1 * ccy + ccy + ty[b];

    // window origin from tile-corner extremes (affine is linear in x,y)
    const float xf0 = (float)cx, xf1 = (float)(cx + TC - 1);
    const float yf0 = (float)ry, yf1 = (float)(ry + TR - 1);
    float xsA = a0 * xf0 + a1 * yf0 + a2;
    float xsB = a0 * xf1 + a1 * yf0 + a2;
    float xsC = a0 * xf0 + a1 * yf1 + a2;
    float xsD = a0 * xf1 + a1 * yf1 + a2;
    float ysA = b0 * xf0 + b1 * yf0 + b2;
    float ysB = b0 * xf1 + b1 * yf0 + b2;
    float ysC = b0 * xf0 + b1 * yf1 + b2;
    float ysD = b0 * xf1 + b1 * yf1 + b2;
    const int x_lo = (int)floorf(fminf(fminf(xsA, xsB), fminf(xsC, xsD))) - 1;
    const int y_lo = (int)floorf(fminf(fminf(ysA, ysB), fminf(ysC, ysD))) - 1;

    __shared__ float win[WR][WROWF];     // 26 * 252 * 4 = 26208 B

    const float* __restrict__ imgb = img + (size_t)b * HWPIX * CC;

    // stage window rows (zero-filled outside the image)
#pragma unroll 2
    for (int rr = 0; rr < WR; rr++) {
        const int yy = y_lo + rr;
        const bool rowok = ((unsigned)yy < (unsigned)HH);
        const float* rowp = imgb + ((size_t)yy * WW + x_lo) * CC;
        if (t < WROWF) {
            const int c  = t / 3;
            const int xx = x_lo + c;
            float v = 0.0f;
            if (rowok && ((unsigned)xx < (unsigned)WW)) v = rowp[t];
            win[rr][t] = v;
        }
    }
    __syncthreads();

    // each thread: 4 consecutive x pixels in one row
    const int tyl = t >> 4;              // 0..15 row within tile
    const int txl = (t & 15) * 4;        // 0..60 col within tile
    const int y   = ry + tyl;
    const int xb  = cx + txl;
    const float yf = (float)y;

    float s0 = 0.f, s1 = 0.f, s2 = 0.f;
    float res[12];

#pragma unroll
    for (int j = 0; j < 4; j++) {
        const float xf = (float)(xb + j);
        const float xs = a0 * xf + a1 * yf + a2;
        const float ys = b0 * xf + b1 * yf + b2;
        const float x0f = floorf(xs);
        const float y0f = floorf(ys);
        const float wx = xs - x0f;
        const float wy = ys - y0f;
        int ci = (int)x0f - x_lo;
        int ri = (int)y0f - y_lo;
        // defensive clamp (window math guarantees in-bounds; this is insurance)
        ci = min(max(ci, 0), WC - 2);
        ri = min(max(ri, 0), WR - 2);

        const float* w0 = &win[ri][ci * 3];
        const float* w1 = &win[ri + 1][ci * 3];

        const float w00 = (1.f - wy) * (1.f - wx);
        const float w01 = (1.f - wy) * wx;
        const float w10 = wy * (1.f - wx);
        const float w11 = wy * wx;

        const float o0 = w00 * w0[0] + w01 * w0[3] + w10 * w1[0] + w11 * w1[3];
        const float o1 = w00 * w0[1] + w01 * w0[4] + w10 * w1[1] + w11 * w1[4];
        const float o2 = w00 * w0[2] + w01 * w0[5] + w10 * w1[2] + w11 * w1[5];
        res[j * 3 + 0] = o0;
        res[j * 3 + 1] = o1;
        res[j * 3 + 2] = o2;
        s0 += o0; s1 += o1; s2 += o2;
    }

    // vectorized store: 12 floats = 3 x float4 (48B-aligned since xb%4==0)
    float4* ob = (float4*)(out + ((size_t)b * HWPIX + (size_t)y * WW + xb) * CC);
    ob[0] = make_float4(res[0], res[1], res[2], res[3]);
    ob[1] = make_float4(res[4], res[5], res[6], res[7]);
    ob[2] = make_float4(res[8], res[9], res[10], res[11]);

    // deterministic block reduction of channel sums
    __shared__ float sm[8][3];
    const int lane = t & 31;
    const int wrp  = t >> 5;
#pragma unroll
    for (int off = 16; off > 0; off >>= 1) {
        s0 += __shfl_down_sync(0xffffffffu, s0, off);
        s1 += __shfl_down_sync(0xffffffffu, s1, off);
        s2 += __shfl_down_sync(0xffffffffu, s2, off);
    }
    if (lane == 0) { sm[wrp][0] = s0; sm[wrp][1] = s1; sm[wrp][2] = s2; }
    __syncthreads();
    if (wrp == 0 && lane < 8) {
        float t0 = sm[lane][0], t1 = sm[lane][1], t2 = sm[lane][2];
#pragma unroll
        for (int off = 4; off > 0; off >>= 1) {
            t0 += __shfl_down_sync(0xffu, t0, off);
            t1 += __shfl_down_sync(0xffu, t1, off);
            t2 += __shfl_down_sync(0xffu, t2, off);
        }
        if (lane == 0) {
            const int blkid = blockIdx.y * 4 + blockIdx.x;   // 0..63
            g_partial[b][blkid][0] = t0;
            g_partial[b][blkid][1] = t1;
            g_partial[b][blkid][2] = t2;
        }
    }
}

// ---------------------------------------------------------------------------
// Kernel 2: per-image mean + per-row cutout bitmasks (one block per image)
// ---------------------------------------------------------------------------
__device__ __forceinline__ unsigned rmask(int x0, int x1, int lo)
{
    int s = x0 - lo; if (s < 0) s = 0;
    int e = x1 - lo; if (e > 32) e = 32;
    if (e <= s) return 0u;
    unsigned me = (e == 32) ? 0xffffffffu : ((1u << e) - 1u);
    unsigned ms = (s == 0)  ? 0u          : ((1u << s) - 1u);
    return me & ~ms;
}

__global__ __launch_bounds__(256) void k_mask(
    const float* __restrict__ fill_is_one,
    const int* __restrict__ hs, const int* __restrict__ ws,
    const int* __restrict__ y0, const int* __restrict__ x0)
{
    const int b = blockIdx.x;
    const int t = threadIdx.x;       // 0..255

    __shared__ int   ry0[KK], ry1[KK], rx0[KK], rx1[KK];
    __shared__ int   rfill[KK];
    __shared__ float smr[2][3];

    if (t < KK) {
        const int k  = t;
        const int hk = hs[b * KK + k];
        const int wk = ws[b * KK + k];
        int y0c = y0[b * KK + k]; if (y0c > HH - hk) y0c = HH - hk;
        int x0c = x0[b * KK + k]; if (x0c > WW - wk) x0c = WW - wk;
        ry0[k] = y0c; ry1[k] = y0c + hk;
        rx0[k] = x0c; rx1[k] = x0c + wk;
        rfill[k] = (fill_is_one[b * KK + k] > 0.5f) ? 1 : 0;
    }

    // mean reduce over 64 partials (threads 0..63 = warps 0..1)
    if (t < 64) {
        float s0 = g_partial[b][t][0];
        float s1 = g_partial[b][t][1];
        float s2 = g_partial[b][t][2];
        const int lane = t & 31;
        const int wrp  = t >> 5;
#pragma unroll
        for (int off = 16; off > 0; off >>= 1) {
            s0 += __shfl_down_sync(0xffffffffu, s0, off);
            s1 += __shfl_down_sync(0xffffffffu, s1, off);
            s2 += __shfl_down_sync(0xffffffffu, s2, off);
        }
        if (lane == 0) { smr[wrp][0] = s0; smr[wrp][1] = s1; smr[wrp][2] = s2; }
    }
    __syncthreads();
    if (t == 0) {
        const float inv = 1.0f / (float)HWPIX;
        g_mean[b][0] = (smr[0][0] + smr[1][0]) * inv;
        g_mean[b][1] = (smr[0][1] + smr[1][1]) * inv;
        g_mean[b][2] = (smr[0][2] + smr[1][2]) * inv;
    }

    // each thread builds the masks for one row
    const int y = t;
    unsigned em[8] = {0,0,0,0,0,0,0,0};
    unsigned bm[8] = {0,0,0,0,0,0,0,0};
#pragma unroll
    for (int k = 0; k < KK; k++) {
        if (y >= ry0[k] && y < ry1[k]) {
            const int xa = rx0[k], xb = rx1[k];
            if (rfill[k]) {
#pragma unroll
                for (int w = 0; w < 8; w++) bm[w] |= rmask(xa, xb, w * 32);
            } else {
#pragma unroll
                for (int w = 0; w < 8; w++) em[w] |= rmask(xa, xb, w * 32);
            }
        }
    }
#pragma unroll
    for (int w = 0; w < 8; w++) {
        g_emask[b][y][w] = em[w];
        g_bmask[b][y][w] = bm[w];
    }
}

// ---------------------------------------------------------------------------
// Kernel 3: contrast/brightness + cutout masks + clip, vectorized float4
// ---------------------------------------------------------------------------
__global__ __launch_bounds__(256) void k_epilogue(
    const float* __restrict__ contrast, const float* __restrict__ brightness,
    float* __restrict__ out)
{
    const int b  = blockIdx.y;
    const int rg = blockIdx.x;           // 0..63, 4 rows each
    const int t  = threadIdx.x;          // 0..255

    __shared__ unsigned sew[4][8];
    __shared__ unsigned sbw[4][8];
    if (t < 64) {
        const int row = t >> 4;          // 0..3
        const int w   = t & 15;          // 0..15
        if (w < 8) sew[row][w] = g_emask[b][rg * 4 + row][w];
        else       sbw[row][w - 8] = g_bmask[b][rg * 4 + row][w - 8];
    }
    __syncthreads();

    const float m0 = g_mean[b][0];
    const float m1 = g_mean[b][1];
    const float m2 = g_mean[b][2];
    const float ct = contrast[b];
    const float br = brightness[b];

    const int p  = rg * 1024 + 4 * t;    // first pixel of this thread
    const int yl = t >> 6;               // row within block (0..3)
    const int x  = (4 * t) & 255;        // x of first pixel (multiple of 4)

    const unsigned ew = sew[yl][x >> 5] >> (x & 31);   // 4 bits: pixels x..x+3
    const unsigned bw = sbw[yl][x >> 5] >> (x & 31);

    float4* base = (float4*)(out + ((size_t)b * HWPIX + p) * CC);
    float4 fa = base[0];
    float4 fb = base[1];
    float4 fc = base[2];

    float v[12] = { fa.x, fa.y, fa.z, fa.w, fb.x, fb.y, fb.z, fb.w,
                    fc.x, fc.y, fc.z, fc.w };
    const float mm[3] = { m0, m1, m2 };

#pragma unroll
    for (int j = 0; j < 12; j++) {
        const int ch = j - (j >= 3) * 3 - (j >= 6) * 3 - (j >= 9) * 3; // j % 3
        const int px = j / 3;                                           // 0..3
        float val = (v[j] - mm[ch]) * ct + mm[ch] + br;
        if ((ew >> px) & 1u) val = 0.0f;
        if ((bw >> px) & 1u) val = 1.0f;
        v[j] = fminf(fmaxf(val, 0.0f), 1.0f);
    }

    fa = make_float4(v[0], v[1], v[2], v[3]);
    fb = make_float4(v[4], v[5], v[6], v[7]);
    fc = make_float4(v[8], v[9], v[10], v[11]);
    base[0] = fa;
    base[1] = fb;
    base[2] = fc;
}

// ---------------------------------------------------------------------------
extern "C" void kernel_launch(void* const* d_in, const int* in_sizes, int n_in,
                              void* d_out, int out_size)
{
    const float* images     = (const float*)d_in[0];
    const float* zoom       = (const float*)d_in[1];
    const float* rot        = (const float*)d_in[2];
    const float* shy        = (const float*)d_in[3];
    const float* ty         = (const float*)d_in[4];
    const float* tx         = (const float*)d_in[5];
    const float* contrast   = (const float*)d_in[6];
    const float* brightness = (const float*)d_in[7];
    const float* fill       = (const float*)d_in[8];
    const int*   hs         = (const int*)d_in[9];
    const int*   ws         = (const int*)d_in[10];
    const int*   y0         = (const int*)d_in[11];
    const int*   x0         = (const int*)d_in[12];
    float* out = (float*)d_out;

    dim3 gwarp(4, 16, BB);
    k_warp<<<gwarp, 256>>>(images, zoom, rot, shy, ty, tx, out);
    k_mask<<<BB, 256>>>(fill, hs, ws, y0, x0);
    dim3 gepi(64, BB);
    k_epilogue<<<gepi, 256>>>(contrast, brightness, out);
}

// round 4
// speedup vs baseline: 1.2617x; 1.2617x over previous
#include <cuda_runtime.h>

#define BB 64
#define HH 256
#define WW 256
#define CC 3
#define KK 20
#define HWPIX (HH * WW)

// k_warp tiling: 16 rows x 64 cols per block
#define TR 16
#define TC 64
#define NBLK_PER_IMG 64
// staged input window (bounds: zoom<=1.15, |rot|<=0.05, |shy|<=0.2 =>
// col span <= 81, row span <= 24)
#define WR 26
#define WC 84

// Scratch (device global: allowed, no allocation)
__device__ float g_partial[BB][NBLK_PER_IMG][3];

// ---------------------------------------------------------------------------
// Kernel 1: smem-staged (RGBX float4) affine bilinear warp + partial sums
// ---------------------------------------------------------------------------
__global__ __launch_bounds__(256, 4) void k_warp(
    const float* __restrict__ img,
    const float* __restrict__ zoom, const float* __restrict__ rot,
    const float* __restrict__ shy,  const float* __restrict__ ty,
    const float* __restrict__ tx,
    float* __restrict__ out)
{
    const int b  = blockIdx.z;
    const int ry = blockIdx.y * TR;
    const int cx = blockIdx.x * TC;
    const int t  = threadIdx.x;          // 0..255

    const float z  = zoom[b];
    const float r  = rot[b];
    const float sh = shy[b];
    const float co = cosf(r), si = sinf(r);
    const float a0 = z * co;
    const float a1 = -z * (si + sh);
    const float b0 = z * si;
    const float b1 = z * co;
    const float ccx = (WW - 1) * 0.5f, ccy = (HH - 1) * 0.5f;
    const float a2 = -a0 * ccx - a1 * ccy + ccx + tx[b];
    const float b2 = -b0 * ccx - b1 * ccy + ccy + ty[b];

    // window origin from tile-corner extremes (affine is linear in x,y)
    const float xf0 = (float)cx, xf1 = (float)(cx + TC - 1);
    const float yf0 = (float)ry, yf1 = (float)(ry + TR - 1);
    const float xsA = a0 * xf0 + a1 * yf0 + a2;
    const float xsB = a0 * xf1 + a1 * yf0 + a2;
    const float xsC = a0 * xf0 + a1 * yf1 + a2;
    const float xsD = a0 * xf1 + a1 * yf1 + a2;
    const float ysA = b0 * xf0 + b1 * yf0 + b2;
    const float ysB = b0 * xf1 + b1 * yf0 + b2;
    const float ysC = b0 * xf0 + b1 * yf1 + b2;
    const float ysD = b0 * xf1 + b1 * yf1 + b2;
    const int x_lo = (int)floorf(fminf(fminf(xsA, xsB), fminf(xsC, xsD))) - 1;
    const int y_lo = (int)floorf(fminf(fminf(ysA, ysB), fminf(ysC, ysD))) - 1;

    __shared__ float4 win[WR][WC];       // 26*84*16 = 34944 B

    const float* __restrict__ imgb = img + (size_t)b * HWPIX * CC;

    // stage: thread = one window pixel; 3 rows x 84 cols per sweep, 9 sweeps
    {
        const int srow = t / 84;         // 0..3 (252..255 idle)
        const int scol = t - srow * 84;
        if (srow < 3) {
            const int xx = x_lo + scol;
            const bool colok = ((unsigned)xx < (unsigned)WW);
#pragma unroll
            for (int i = 0; i < 9; i++) {
                const int rr = i * 3 + srow;
                if (rr < WR) {
                    const int yy = y_lo + rr;
                    float f0 = 0.f, f1 = 0.f, f2 = 0.f;
                    if (colok && ((unsigned)yy < (unsigned)HH)) {
                        const float* p = imgb + ((size_t)yy * WW + xx) * CC;
                        f0 = p[0]; f1 = p[1]; f2 = p[2];
                    }
                    win[rr][scol] = make_float4(f0, f1, f2, 0.f);
                }
            }
        }
    }
    __syncthreads();

    // each thread: 4 consecutive x pixels in one row
    const int tyl = t >> 4;              // 0..15
    const int txl = (t & 15) * 4;        // 0..60
    const int y   = ry + tyl;
    const int xb  = cx + txl;
    const float yf = (float)y;
    const float ax = a1 * yf + a2;       // xs = a0*x + ax
    const float bx = b1 * yf + b2;       // ys = b0*x + bx

    float s0 = 0.f, s1 = 0.f, s2 = 0.f;
    float res[12];

#pragma unroll
    for (int j = 0; j < 4; j++) {
        const float xf = (float)(xb + j);
        const float xs = a0 * xf + ax;
        const float ys = b0 * xf + bx;
        const float x0f = floorf(xs);
        const float y0f = floorf(ys);
        const float wx = xs - x0f;
        const float wy = ys - y0f;
        int ci = (int)x0f - x_lo;
        int ri = (int)y0f - y_lo;
        ci = min(max(ci, 0), WC - 2);    // defensive (window math guarantees)
        ri = min(max(ri, 0), WR - 2);

        const float4 c00 = win[ri][ci];
        const float4 c01 = win[ri][ci + 1];
        const float4 c10 = win[ri + 1][ci];
        const float4 c11 = win[ri + 1][ci + 1];

        const float w00 = (1.f - wy) * (1.f - wx);
        const float w01 = (1.f - wy) * wx;
        const float w10 = wy * (1.f - wx);
        const float w11 = wy * wx;

        const float o0 = w00 * c00.x + w01 * c01.x + w10 * c10.x + w11 * c11.x;
        const float o1 = w00 * c00.y + w01 * c01.y + w10 * c10.y + w11 * c11.y;
        const float o2 = w00 * c00.z + w01 * c01.z + w10 * c10.z + w11 * c11.z;
        res[j * 3 + 0] = o0;
        res[j * 3 + 1] = o1;
        res[j * 3 + 2] = o2;
        s0 += o0; s1 += o1; s2 += o2;
    }

    float4* ob = (float4*)(out + ((size_t)b * HWPIX + (size_t)y * WW + xb) * CC);
    ob[0] = make_float4(res[0], res[1], res[2], res[3]);
    ob[1] = make_float4(res[4], res[5], res[6], res[7]);
    ob[2] = make_float4(res[8], res[9], res[10], res[11]);

    // deterministic block reduction of channel sums
    __shared__ float sm[8][3];
    const int lane = t & 31;
    const int wrp  = t >> 5;
#pragma unroll
    for (int off = 16; off > 0; off >>= 1) {
        s0 += __shfl_down_sync(0xffffffffu, s0, off);
        s1 += __shfl_down_sync(0xffffffffu, s1, off);
        s2 += __shfl_down_sync(0xffffffffu, s2, off);
    }
    if (lane == 0) { sm[wrp][0] = s0; sm[wrp][1] = s1; sm[wrp][2] = s2; }
    __syncthreads();
    if (wrp == 0 && lane < 8) {
        float t0 = sm[lane][0], t1 = sm[lane][1], t2 = sm[lane][2];
#pragma unroll
        for (int off = 4; off > 0; off >>= 1) {
            t0 += __shfl_down_sync(0xffu, t0, off);
            t1 += __shfl_down_sync(0xffu, t1, off);
            t2 += __shfl_down_sync(0xffu, t2, off);
        }
        if (lane == 0) {
            const int blkid = blockIdx.y * 4 + blockIdx.x;
            g_partial[b][blkid][0] = t0;
            g_partial[b][blkid][1] = t1;
            g_partial[b][blkid][2] = t2;
        }
    }
}

// ---------------------------------------------------------------------------
// Kernel 2: fused mean-reduce + per-row masks + contrast/brightness + cutouts
// Block = 256 thr = 4 rows (1024 px). Grid = (64 row-groups, 64 images).
// ---------------------------------------------------------------------------
__device__ __forceinline__ unsigned rmask(int x0, int x1, int lo)
{
    int s = x0 - lo; if (s < 0) s = 0;
    int e = x1 - lo; if (e > 32) e = 32;
    if (e <= s) return 0u;
    unsigned me = (e == 32) ? 0xffffffffu : ((1u << e) - 1u);
    unsigned ms = (s == 0)  ? 0u          : ((1u << s) - 1u);
    return me & ~ms;
}

__global__ __launch_bounds__(256) void k_epilogue(
    const float* __restrict__ contrast, const float* __restrict__ brightness,
    const float* __restrict__ fill_is_one,
    const int* __restrict__ hs, const int* __restrict__ ws,
    const int* __restrict__ y0, const int* __restrict__ x0,
    float* __restrict__ out)
{
    const int b  = blockIdx.y;
    const int rg = blockIdx.x;           // 0..63, 4 rows each
    const int t  = threadIdx.x;          // 0..255

    __shared__ int ry0[KK], ry1[KK], rx0[KK], rx1[KK], rfill[KK];
    __shared__ float smr[2][3];
    __shared__ float smean[3];
    __shared__ unsigned sew[4][8];
    __shared__ unsigned sbw[4][8];

    // phase 1: rect load (t<20) + mean partial reduce (threads 64..127)
    if (t < KK) {
        const int k  = t;
        const int hk = hs[b * KK + k];
        const int wk = ws[b * KK + k];
        int yc = y0[b * KK + k]; if (yc > HH - hk) yc = HH - hk;
        int xc = x0[b * KK + k]; if (xc > WW - wk) xc = WW - wk;
        ry0[k] = yc; ry1[k] = yc + hk;
        rx0[k] = xc; rx1[k] = xc + wk;
        rfill[k] = (fill_is_one[b * KK + k] > 0.5f) ? 1 : 0;
    }
    if (t >= 64 && t < 128) {
        const int tt = t - 64;           // 0..63
        float s0 = g_partial[b][tt][0];
        float s1 = g_partial[b][tt][1];
        float s2 = g_partial[b][tt][2];
        const int lane = tt & 31;
        const int wrp  = tt >> 5;
#pragma unroll
        for (int off = 16; off > 0; off >>= 1) {
            s0 += __shfl_down_sync(0xffffffffu, s0, off);
            s1 += __shfl_down_sync(0xffffffffu, s1, off);
            s2 += __shfl_down_sync(0xffffffffu, s2, off);
        }
        if (lane == 0) { smr[wrp][0] = s0; smr[wrp][1] = s1; smr[wrp][2] = s2; }
    }
    __syncthreads();
    if (t == 0) {
        const float inv = 1.0f / (float)HWPIX;
        smean[0] = (smr[0][0] + smr[1][0]) * inv;
        smean[1] = (smr[0][1] + smr[1][1]) * inv;
        smean[2] = (smr[0][2] + smr[1][2]) * inv;
    }
    // phase 2: build 4-row bitmasks (threads 0..31)
    if (t < 32) {
        const int row = rg * 4 + (t >> 3);
        const int w   = t & 7;
        unsigned em = 0u, bm = 0u;
#pragma unroll
        for (int k = 0; k < KK; k++) {
            if (row >= ry0[k] && row < ry1[k]) {
                const unsigned m = rmask(rx0[k], rx1[k], w * 32);
                if (rfill[k]) bm |= m; else em |= m;
            }
        }
        sew[t >> 3][w] = em;
        sbw[t >> 3][w] = bm;
    }
    __syncthreads();

    const float m0 = smean[0];
    const float m1 = smean[1];
    const float m2 = smean[2];
    const float ct = contrast[b];
    const float br = brightness[b];

    const int p  = rg * 1024 + 4 * t;
    const int yl = t >> 6;
    const int x  = (4 * t) & 255;

    const unsigned ew = sew[yl][x >> 5] >> (x & 31);
    const unsigned bw = sbw[yl][x >> 5] >> (x & 31);

    float4* base = (float4*)(out + ((size_t)b * HWPIX + p) * CC);
    float4 fa = base[0];
    float4 fb = base[1];
    float4 fc = base[2];

    float v[12] = { fa.x, fa.y, fa.z, fa.w, fb.x, fb.y, fb.z, fb.w,
                    fc.x, fc.y, fc.z, fc.w };
    const float mm[3] = { m0, m1, m2 };

#pragma unroll
    for (int j = 0; j < 12; j++) {
        const int ch = j - (j >= 3) * 3 - (j >= 6) * 3 - (j >= 9) * 3; // j % 3
        const int px = j / 3;
        float val = (v[j] - mm[ch]) * ct + mm[ch] + br;
        if ((ew >> px) & 1u) val = 0.0f;
        if ((bw >> px) & 1u) val = 1.0f;
        v[j] = fminf(fmaxf(val, 0.0f), 1.0f);
    }

    base[0] = make_float4(v[0], v[1], v[2], v[3]);
    base[1] = make_float4(v[4], v[5], v[6], v[7]);
    base[2] = make_float4(v[8], v[9], v[10], v[11]);
}

// ---------------------------------------------------------------------------
extern "C" void kernel_launch(void* const* d_in, const int* in_sizes, int n_in,
                              void* d_out, int out_size)
{
    const float* images     = (const float*)d_in[0];
    const float* zoom       = (const float*)d_in[1];
    const float* rot        = (const float*)d_in[2];
    const float* shy        = (const float*)d_in[3];
    const float* ty         = (const float*)d_in[4];
    const float* tx         = (const float*)d_in[5];
    const float* contrast   = (const float*)d_in[6];
    const float* brightness = (const float*)d_in[7];
    const float* fill       = (const float*)d_in[8];
    const int*   hs         = (const int*)d_in[9];
    const int*   ws         = (const int*)d_in[10];
    const int*   y0         = (const int*)d_in[11];
    const int*   x0         = (const int*)d_in[12];
    float* out = (float*)d_out;

    dim3 gwarp(4, 16, BB);
    k_warp<<<gwarp, 256>>>(images, zoom, rot, shy, ty, tx, out);
    dim3 gepi(64, BB);
    k_epilogue<<<gepi, 256>>>(contrast, brightness, fill, hs, ws, y0, x0, out);
}